// round 9
// baseline (speedup 1.0000x reference)
#include <cuda_runtime.h>

#define BATCH   8
#define SEQ     4096
#define DIM     64
#define DS      16
#define CHUNK   64
#define NCHUNK  (SEQ / CHUNK)        // 64
#define ROWS    (BATCH * SEQ)        // 32768
#define NSUPER  8                    // superchunks per batch
#define SCH     (NCHUNK / NSUPER)    // 8 chunks per superchunk

// Scratch (device globals; no allocations allowed)
__device__ float g_A  [ROWS * 256];            // per-timestep A_t [row][i*16+l]
__device__ float g_Bx [ROWS * DS];             // per-timestep Bx_t
__device__ float g_P  [BATCH * NCHUNK * 256];  // per-chunk cumulative transition
__device__ float g_v  [BATCH * NCHUNK * DS];   // per-chunk aggregate input
__device__ float g_h0 [BATCH * NCHUNK * DS];   // state entering each chunk
__device__ float g_H  [ROWS * DS];             // h_t for every timestep
__device__ float g_SP [BATCH * NSUPER * 256];  // per-superchunk transition
__device__ float g_Sv [BATCH * NSUPER * DS];   // per-superchunk aggregate
__device__ float g_sh0[BATCH * NSUPER * DS];   // state entering each superchunk

// ---------------------------------------------------------------------------
// helpers: tf32 convert + m16n8k8 tf32 mma
// ---------------------------------------------------------------------------
__device__ __forceinline__ float f2tf(float f) {
    unsigned u;
    asm("cvt.rna.tf32.f32 %0, %1;" : "=r"(u) : "f"(f));
    return __uint_as_float(u);
}
__device__ __forceinline__ void mma8(float* c,
                                     unsigned a0, unsigned a1, unsigned a2, unsigned a3,
                                     unsigned b0, unsigned b1) {
    asm volatile(
        "mma.sync.aligned.m16n8k8.row.col.f32.tf32.tf32.f32 "
        "{%0,%1,%2,%3},{%4,%5,%6,%7},{%8,%9},{%0,%1,%2,%3};"
        : "+f"(c[0]), "+f"(c[1]), "+f"(c[2]), "+f"(c[3])
        : "r"(a0), "r"(a1), "r"(a2), "r"(a3), "r"(b0), "r"(b1));
}
__device__ __forceinline__ unsigned fu(float f) { return __float_as_uint(f); }

// ---------------------------------------------------------------------------
// Kernel 1 (tensor, fused): per 128-row stripe, loop 20 N-tiles of 64:
//   tiles 0..3  : A = X @ W_A + b_A -> g_A
//   tiles 4..19 : Bm_n = X @ W_B[:,n,:] + b_B ; Bx[:,n] = Bm_n . x -> g_Bx
// X loaded/converted ONCE per stripe; W tiles register-prefetched.
// grid (ROWS/128, 2): y=0 -> tiles 0..9, y=1 -> tiles 10..19.
// ---------------------------------------------------------------------------
#define KP_WS   (128 * 68)
#define KP_RED  (KP_WS + 64 * 68)
#define KP_SMEM (KP_RED + 128 * 2)

__global__ __launch_bounds__(256) void k_proj(const float* __restrict__ x,
                                              const float* __restrict__ W_A,
                                              const float* __restrict__ b_A,
                                              const float* __restrict__ W_B,
                                              const float* __restrict__ b_B) {
    extern __shared__ float sm[];
    float* Xs  = sm;            // [128][68] tf32 x
    float* Ws  = sm + KP_WS;    // [64][68]  tf32 current W tile
    float* red = sm + KP_RED;   // [128][2]  Bx cross-warp reduce
    const int tid = threadIdx.x;
    const int m0 = blockIdx.x * 128;
    const int j0 = blockIdx.y * 10, j1 = j0 + 10;

#pragma unroll
    for (int it = 0; it < 8; it++) {
        int i4 = it * 256 + tid;
        int row = i4 >> 4, c4 = (i4 & 15) * 4;
        float4 v = *(const float4*)&x[(long)(m0 + row) * 64 + c4];
        Xs[row * 68 + c4 + 0] = f2tf(v.x);
        Xs[row * 68 + c4 + 1] = f2tf(v.y);
        Xs[row * 68 + c4 + 2] = f2tf(v.z);
        Xs[row * 68 + c4 + 3] = f2tf(v.w);
    }

    // W tile load indices: 64x64 = 1024 float4, 4 per thread
    int wk[4], wd[4];
#pragma unroll
    for (int it = 0; it < 4; it++) {
        int i4 = it * 256 + tid;
        wk[it] = i4 >> 4;
        wd[it] = (i4 & 15) * 4;
    }
    float4 wreg[4];
#pragma unroll
    for (int it = 0; it < 4; it++)
        wreg[it] = (j0 < 4)
            ? *(const float4*)&W_A[(long)wk[it] * 256 + j0 * 64 + wd[it]]
            : *(const float4*)&W_B[(long)wk[it] * 1024 + (j0 - 4) * 64 + wd[it]];

    const int wid = tid >> 5, lane = tid & 31;
    const int g = lane >> 2, tig = lane & 3;
    const int wm = wid & 3, wn = wid >> 2;     // 4 M-warps x 2 N-warps
    const int mbase = wm * 32, nbase = wn * 32;

    for (int j = j0; j < j1; j++) {
        __syncthreads();   // Ws (and red) free to overwrite
#pragma unroll
        for (int it = 0; it < 4; it++) {
            Ws[wk[it] * 68 + wd[it] + 0] = f2tf(wreg[it].x);
            Ws[wk[it] * 68 + wd[it] + 1] = f2tf(wreg[it].y);
            Ws[wk[it] * 68 + wd[it] + 2] = f2tf(wreg[it].z);
            Ws[wk[it] * 68 + wd[it] + 3] = f2tf(wreg[it].w);
        }
        __syncthreads();
        if (j + 1 < j1) {
#pragma unroll
            for (int it = 0; it < 4; it++)
                wreg[it] = (j + 1 < 4)
                    ? *(const float4*)&W_A[(long)wk[it] * 256 + (j + 1) * 64 + wd[it]]
                    : *(const float4*)&W_B[(long)wk[it] * 1024 + (j - 3) * 64 + wd[it]];
        }

        float c[2][4][4];
#pragma unroll
        for (int mt = 0; mt < 2; mt++)
#pragma unroll
            for (int nt = 0; nt < 4; nt++)
#pragma unroll
                for (int jj = 0; jj < 4; jj++) c[mt][nt][jj] = 0.f;

#pragma unroll
        for (int ks = 0; ks < 8; ks++) {
            const int k0 = ks * 8;
            unsigned a[2][4];
#pragma unroll
            for (int mt = 0; mt < 2; mt++) {
                int r = mbase + mt * 16 + g;
                a[mt][0] = fu(Xs[r * 68 + k0 + tig]);
                a[mt][1] = fu(Xs[(r + 8) * 68 + k0 + tig]);
                a[mt][2] = fu(Xs[r * 68 + k0 + tig + 4]);
                a[mt][3] = fu(Xs[(r + 8) * 68 + k0 + tig + 4]);
            }
            unsigned b[4][2];
#pragma unroll
            for (int nt = 0; nt < 4; nt++) {
                int n = nbase + nt * 8 + g;
                b[nt][0] = fu(Ws[(k0 + tig) * 68 + n]);
                b[nt][1] = fu(Ws[(k0 + tig + 4) * 68 + n]);
            }
#pragma unroll
            for (int mt = 0; mt < 2; mt++)
#pragma unroll
                for (int nt = 0; nt < 4; nt++)
                    mma8(c[mt][nt], a[mt][0], a[mt][1], a[mt][2], a[mt][3],
                         b[nt][0], b[nt][1]);
        }

        if (j < 4) {
            // A tile: add bias, store to g_A
#pragma unroll
            for (int mt = 0; mt < 2; mt++)
#pragma unroll
                for (int nt = 0; nt < 4; nt++) {
                    int row = m0 + mbase + mt * 16 + g;
                    int col = j * 64 + nbase + nt * 8 + tig * 2;
                    float b0 = b_A[col], b1 = b_A[col + 1];
                    *(float2*)&g_A[(long)row * 256 + col] =
                        make_float2(c[mt][nt][0] + b0, c[mt][nt][1] + b1);
                    *(float2*)&g_A[(long)(row + 8) * 256 + col] =
                        make_float2(c[mt][nt][2] + b0, c[mt][nt][3] + b1);
                }
        } else {
            // B tile (one n): fused Bx epilogue
            const int n_idx = j - 4;
            const int r0 = mbase + g, r0b = r0 + 8;
            const int r1 = mbase + 16 + g, r1b = r1 + 8;
            float p00 = 0.f, p01 = 0.f, p10 = 0.f, p11 = 0.f;
#pragma unroll
            for (int nt = 0; nt < 4; nt++) {
                int dloc = nbase + nt * 8 + tig * 2;
                float bv0 = b_B[n_idx * 64 + dloc];
                float bv1 = b_B[n_idx * 64 + dloc + 1];
                float x00 = Xs[r0 * 68 + dloc],  x01 = Xs[r0 * 68 + dloc + 1];
                float x10 = Xs[r0b * 68 + dloc], x11 = Xs[r0b * 68 + dloc + 1];
                float x20 = Xs[r1 * 68 + dloc],  x21 = Xs[r1 * 68 + dloc + 1];
                float x30 = Xs[r1b * 68 + dloc], x31 = Xs[r1b * 68 + dloc + 1];
                p00 += (c[0][nt][0] + bv0) * x00 + (c[0][nt][1] + bv1) * x01;
                p01 += (c[0][nt][2] + bv0) * x10 + (c[0][nt][3] + bv1) * x11;
                p10 += (c[1][nt][0] + bv0) * x20 + (c[1][nt][1] + bv1) * x21;
                p11 += (c[1][nt][2] + bv0) * x30 + (c[1][nt][3] + bv1) * x31;
            }
            p00 += __shfl_xor_sync(0xffffffffu, p00, 1, 4);
            p00 += __shfl_xor_sync(0xffffffffu, p00, 2, 4);
            p01 += __shfl_xor_sync(0xffffffffu, p01, 1, 4);
            p01 += __shfl_xor_sync(0xffffffffu, p01, 2, 4);
            p10 += __shfl_xor_sync(0xffffffffu, p10, 1, 4);
            p10 += __shfl_xor_sync(0xffffffffu, p10, 2, 4);
            p11 += __shfl_xor_sync(0xffffffffu, p11, 1, 4);
            p11 += __shfl_xor_sync(0xffffffffu, p11, 2, 4);
            if (tig == 0) {
                red[r0 * 2 + wn]  = p00;
                red[r0b * 2 + wn] = p01;
                red[r1 * 2 + wn]  = p10;
                red[r1b * 2 + wn] = p11;
            }
            __syncthreads();
            if (tid < 128)
                g_Bx[(long)(m0 + tid) * DS + n_idx] = red[tid * 2] + red[tid * 2 + 1];
        }
    }
}

// ---------------------------------------------------------------------------
// Kernel 1c: per-chunk P,v via binary tree combine (6 levels)
// ---------------------------------------------------------------------------
#define MSTRIDE 272
#define CK_BUFA 0
#define CK_BUFB (32 * MSTRIDE)
#define CK_VX   (2 * 32 * MSTRIDE)
#define CK_VA   (CK_VX + 64 * 16)
#define CK_VB   (CK_VA + 32 * 16)
#define CK_SMEM (CK_VB + 32 * 16)

__global__ __launch_bounds__(256) void k_chunk() {
    extern __shared__ float sm[];
    float* bufA = sm + CK_BUFA;
    float* bufB = sm + CK_BUFB;
    float* VX   = sm + CK_VX;
    float* Va   = sm + CK_VA;
    float* Vb   = sm + CK_VB;
    const int tid = threadIdx.x;
    const int bc = blockIdx.x;
    const long rowbase = (long)bc * CHUNK;

#pragma unroll
    for (int it = 0; it < 8; it++) {
        int i4 = it * 256 + tid;
        int m = i4 >> 6, e4 = (i4 & 63) * 4;
        *(float4*)&bufA[m * MSTRIDE + e4] =
            *(const float4*)&g_A[(rowbase + 2 * m) * 256 + e4];
    }
    *(float4*)&VX[tid * 4] = *(const float4*)&g_Bx[rowbase * DS + tid * 4];
    __syncthreads();

#pragma unroll
    for (int rep = 0; rep < 2; rep++) {
        int r = rep * 256 + tid;
        int m = r >> 4, i = r & 15;
        const float* arow = &g_A[(rowbase + 2 * m + 1) * 256 + i * 16];
        float4 a0 = *(const float4*)&arow[0];
        float4 a1 = *(const float4*)&arow[4];
        float4 a2 = *(const float4*)&arow[8];
        float4 a3 = *(const float4*)&arow[12];
        float av[16] = {a0.x, a0.y, a0.z, a0.w, a1.x, a1.y, a1.z, a1.w,
                        a2.x, a2.y, a2.z, a2.w, a3.x, a3.y, a3.z, a3.w};
        float acc[16];
#pragma unroll
        for (int l = 0; l < 16; l++) acc[l] = 0.f;
        float accv = VX[(2 * m + 1) * 16 + i];
#pragma unroll
        for (int q = 0; q < 16; q++) {
            float aq = av[q];
            float4 b0 = *(const float4*)&bufA[m * MSTRIDE + q * 16 + 0];
            float4 b1 = *(const float4*)&bufA[m * MSTRIDE + q * 16 + 4];
            float4 b2 = *(const float4*)&bufA[m * MSTRIDE + q * 16 + 8];
            float4 b3 = *(const float4*)&bufA[m * MSTRIDE + q * 16 + 12];
            acc[0]  += aq * b0.x; acc[1]  += aq * b0.y;
            acc[2]  += aq * b0.z; acc[3]  += aq * b0.w;
            acc[4]  += aq * b1.x; acc[5]  += aq * b1.y;
            acc[6]  += aq * b1.z; acc[7]  += aq * b1.w;
            acc[8]  += aq * b2.x; acc[9]  += aq * b2.y;
            acc[10] += aq * b2.z; acc[11] += aq * b2.w;
            acc[12] += aq * b3.x; acc[13] += aq * b3.y;
            acc[14] += aq * b3.z; acc[15] += aq * b3.w;
            accv += aq * VX[2 * m * 16 + q];
        }
#pragma unroll
        for (int l4 = 0; l4 < 4; l4++)
            *(float4*)&bufB[m * MSTRIDE + i * 16 + l4 * 4] =
                make_float4(acc[l4 * 4], acc[l4 * 4 + 1],
                            acc[l4 * 4 + 2], acc[l4 * 4 + 3]);
        Vb[m * 16 + i] = accv;
    }
    __syncthreads();

    float* src = bufB; float* dst = bufA;
    float* vs = Vb;    float* vd = Va;
#pragma unroll
    for (int lev = 1; lev <= 5; lev++) {
        int nmerge = 32 >> lev;
        int rows = nmerge * 16;
        if (tid < rows) {
            int m = tid >> 4, i = tid & 15;
            const float* a1p = &src[(2 * m + 1) * MSTRIDE + i * 16];
            float4 a0 = *(const float4*)&a1p[0];
            float4 a1 = *(const float4*)&a1p[4];
            float4 a2 = *(const float4*)&a1p[8];
            float4 a3 = *(const float4*)&a1p[12];
            float av[16] = {a0.x, a0.y, a0.z, a0.w, a1.x, a1.y, a1.z, a1.w,
                            a2.x, a2.y, a2.z, a2.w, a3.x, a3.y, a3.z, a3.w};
            float acc[16];
#pragma unroll
            for (int l = 0; l < 16; l++) acc[l] = 0.f;
            float accv = vs[(2 * m + 1) * 16 + i];
#pragma unroll
            for (int q = 0; q < 16; q++) {
                float aq = av[q];
                const float* bp = &src[2 * m * MSTRIDE + q * 16];
                float4 b0 = *(const float4*)&bp[0];
                float4 b1 = *(const float4*)&bp[4];
                float4 b2 = *(const float4*)&bp[8];
                float4 b3 = *(const float4*)&bp[12];
                acc[0]  += aq * b0.x; acc[1]  += aq * b0.y;
                acc[2]  += aq * b0.z; acc[3]  += aq * b0.w;
                acc[4]  += aq * b1.x; acc[5]  += aq * b1.y;
                acc[6]  += aq * b1.z; acc[7]  += aq * b1.w;
                acc[8]  += aq * b2.x; acc[9]  += aq * b2.y;
                acc[10] += aq * b2.z; acc[11] += aq * b2.w;
                acc[12] += aq * b3.x; acc[13] += aq * b3.y;
                acc[14] += aq * b3.z; acc[15] += aq * b3.w;
                accv += aq * vs[2 * m * 16 + q];
            }
#pragma unroll
            for (int l4 = 0; l4 < 4; l4++)
                *(float4*)&dst[m * MSTRIDE + i * 16 + l4 * 4] =
                    make_float4(acc[l4 * 4], acc[l4 * 4 + 1],
                                acc[l4 * 4 + 2], acc[l4 * 4 + 3]);
            vd[m * 16 + i] = accv;
        }
        __syncthreads();
        float* t = src; src = dst; dst = t;
        float* tv = vs; vs = vd; vd = tv;
    }

    g_P[(long)bc * 256 + tid] = src[tid];
    if (tid < 16) g_v[bc * DS + tid] = vs[tid];
}

// ---------------------------------------------------------------------------
// Kernel 1d: superchunk combine (tree over 8 chunk (P,v) -> (SP,Sv))
// ---------------------------------------------------------------------------
#define SST 260
__global__ __launch_bounds__(256) void k_super() {
    __shared__ float P[2][8 * SST];
    __shared__ float V[2][8 * 16];
    const int tid = threadIdx.x;
    const int bs = blockIdx.x;                  // b*NSUPER + s
    const long cbase = (long)bs * SCH;

#pragma unroll
    for (int e = 0; e < 8; e++) {
        int idx = e * 256 + tid;
        int m = idx >> 8, ij = idx & 255;
        P[0][m * SST + ij] = g_P[(cbase + m) * 256 + ij];
    }
    if (tid < 128) V[0][tid] = g_v[cbase * DS + tid];
    __syncthreads();

    int cur = 0;
#pragma unroll
    for (int lev = 0; lev < 3; lev++) {
        int nm = 4 >> lev;
        int elems = nm * 256;
#pragma unroll
        for (int e = 0; e < 4; e++) {
            int idx = e * 256 + tid;
            if (idx < elems) {
                int m = idx >> 8, ij = idx & 255;
                int i = ij >> 4, jj = ij & 15;
                const float* P1 = &P[cur][(2 * m + 1) * SST + i * 16];
                const float* P0 = &P[cur][2 * m * SST];
                float s = 0.f;
#pragma unroll
                for (int q = 0; q < 16; q++) s += P1[q] * P0[q * 16 + jj];
                P[cur ^ 1][m * SST + ij] = s;
                if (jj == 0) {
                    float sv = V[cur][(2 * m + 1) * 16 + i];
                    const float* V0 = &V[cur][2 * m * 16];
#pragma unroll
                    for (int q = 0; q < 16; q++) sv += P1[q] * V0[q];
                    V[cur ^ 1][m * 16 + i] = sv;
                }
            }
        }
        __syncthreads();
        cur ^= 1;
    }

    g_SP[(long)bs * 256 + tid] = P[cur][tid];
    if (tid < 16) g_Sv[bs * DS + tid] = V[cur][tid];
}

// ---------------------------------------------------------------------------
// Kernel 2: sequential scan over 8 superchunks per batch
// ---------------------------------------------------------------------------
__global__ __launch_bounds__(32) void k_scan2() {
    const int b = blockIdx.x;
    const int lane = threadIdx.x;
    const long base = (long)b * NSUPER;

    float h[16];
#pragma unroll
    for (int q = 0; q < 16; q++) h[q] = 0.f;
    float mine = 0.f;

    float4 p0 = {0,0,0,0}, p1 = p0, p2 = p0, p3 = p0;
    float v = 0.f;
    if (lane < 16) {
        const float* P = &g_SP[base * 256 + lane * 16];
        p0 = *(const float4*)&P[0];
        p1 = *(const float4*)&P[4];
        p2 = *(const float4*)&P[8];
        p3 = *(const float4*)&P[12];
        v = g_Sv[base * DS + lane];
    }

    for (int s = 0; s < NSUPER; s++) {
        float4 q0 = p0, q1 = p1, q2 = p2, q3 = p3;
        float vn = v;
        if (lane < 16 && s + 1 < NSUPER) {
            const float* Pn = &g_SP[(base + s + 1) * 256 + lane * 16];
            q0 = *(const float4*)&Pn[0];
            q1 = *(const float4*)&Pn[4];
            q2 = *(const float4*)&Pn[8];
            q3 = *(const float4*)&Pn[12];
            vn = g_Sv[(base + s + 1) * DS + lane];
        }
        float hn = 0.f;
        if (lane < 16) {
            g_sh0[(base + s) * DS + lane] = mine;
            float s0 = v + p0.x * h[0] + p0.y * h[1] + p0.z * h[2] + p0.w * h[3];
            float s1 = p1.x * h[4] + p1.y * h[5] + p1.z * h[6] + p1.w * h[7];
            float s2 = p2.x * h[8] + p2.y * h[9] + p2.z * h[10] + p2.w * h[11];
            float s3 = p3.x * h[12] + p3.y * h[13] + p3.z * h[14] + p3.w * h[15];
            hn = (s0 + s1) + (s2 + s3);
            mine = hn;
        }
#pragma unroll
        for (int q = 0; q < 16; q++)
            h[q] = __shfl_sync(0xffffffffu, hn, q);
        p0 = q0; p1 = q1; p2 = q2; p3 = q3; v = vn;
    }
}

// ---------------------------------------------------------------------------
// Kernel 2b: within-superchunk chunk-level scan (8 steps) -> g_h0
// ---------------------------------------------------------------------------
__global__ __launch_bounds__(32) void k_mid() {
    const int bs = blockIdx.x;
    const int lane = threadIdx.x;
    const long cbase = (long)bs * SCH;

    float hv = (lane < 16) ? g_sh0[bs * DS + lane] : 0.f;
    float h[16];
#pragma unroll
    for (int q = 0; q < 16; q++) h[q] = __shfl_sync(0xffffffffu, hv, q);
    float mine = hv;

    float4 p0 = {0,0,0,0}, p1 = p0, p2 = p0, p3 = p0;
    float v = 0.f;
    if (lane < 16) {
        const float* P = &g_P[cbase * 256 + lane * 16];
        p0 = *(const float4*)&P[0];
        p1 = *(const float4*)&P[4];
        p2 = *(const float4*)&P[8];
        p3 = *(const float4*)&P[12];
        v = g_v[cbase * DS + lane];
    }

    for (int c = 0; c < SCH; c++) {
        float4 q0 = p0, q1 = p1, q2 = p2, q3 = p3;
        float vn = v;
        if (lane < 16 && c + 1 < SCH) {
            const float* Pn = &g_P[(cbase + c + 1) * 256 + lane * 16];
            q0 = *(const float4*)&Pn[0];
            q1 = *(const float4*)&Pn[4];
            q2 = *(const float4*)&Pn[8];
            q3 = *(const float4*)&Pn[12];
            vn = g_v[(cbase + c + 1) * DS + lane];
        }
        float hn = 0.f;
        if (lane < 16) {
            g_h0[(cbase + c) * DS + lane] = mine;
            float s0 = v + p0.x * h[0] + p0.y * h[1] + p0.z * h[2] + p0.w * h[3];
            float s1 = p1.x * h[4] + p1.y * h[5] + p1.z * h[6] + p1.w * h[7];
            float s2 = p2.x * h[8] + p2.y * h[9] + p2.z * h[10] + p2.w * h[11];
            float s3 = p3.x * h[12] + p3.y * h[13] + p3.z * h[14] + p3.w * h[15];
            hn = (s0 + s1) + (s2 + s3);
            mine = hn;
        }
#pragma unroll
        for (int q = 0; q < 16; q++)
            h[q] = __shfl_sync(0xffffffffu, hn, q);
        p0 = q0; p1 = q1; p2 = q2; p3 = q3; v = vn;
    }
}

// ---------------------------------------------------------------------------
// Kernel 2c: per-chunk replay -> g_H
// ---------------------------------------------------------------------------
__global__ __launch_bounds__(32) void k_replay() {
    const int bc = blockIdx.x;
    const int lane = threadIdx.x;
    const long rowbase = (long)bc * CHUNK;

    float h[16];
#pragma unroll
    for (int q = 0; q < 16; q++) h[q] = g_h0[bc * DS + q];

    float4 a0 = {0,0,0,0}, a1 = a0, a2 = a0, a3 = a0;
    float bx = 0.f;
    if (lane < 16) {
        const float* Arow = &g_A[rowbase * 256 + lane * 16];
        a0 = *(const float4*)&Arow[0];
        a1 = *(const float4*)&Arow[4];
        a2 = *(const float4*)&Arow[8];
        a3 = *(const float4*)&Arow[12];
        bx = g_Bx[rowbase * DS + lane];
    }
    for (int t = 0; t < CHUNK; t++) {
        float4 n0 = a0, n1 = a1, n2 = a2, n3 = a3;
        float bxn = bx;
        if (lane < 16 && t + 1 < CHUNK) {
            const float* An = &g_A[(rowbase + t + 1) * 256 + lane * 16];
            n0 = *(const float4*)&An[0];
            n1 = *(const float4*)&An[4];
            n2 = *(const float4*)&An[8];
            n3 = *(const float4*)&An[12];
            bxn = g_Bx[(rowbase + t + 1) * DS + lane];
        }
        float hn = 0.f;
        if (lane < 16) {
            float s0 = bx + a0.x * h[0] + a0.y * h[1] + a0.z * h[2] + a0.w * h[3];
            float s1 = a1.x * h[4] + a1.y * h[5] + a1.z * h[6] + a1.w * h[7];
            float s2 = a2.x * h[8] + a2.y * h[9] + a2.z * h[10] + a2.w * h[11];
            float s3 = a3.x * h[12] + a3.y * h[13] + a3.z * h[14] + a3.w * h[15];
            hn = (s0 + s1) + (s2 + s3);
            g_H[(rowbase + t) * DS + lane] = hn;
        }
#pragma unroll
        for (int q = 0; q < 16; q++)
            h[q] = __shfl_sync(0xffffffffu, hn, q);
        a0 = n0; a1 = n1; a2 = n2; a3 = n3; bx = bxn;
    }
}

// ---------------------------------------------------------------------------
// Kernel 3 (tensor): out[m,d] = sum_n h[m,n] * (x @ W_C[:,n,:])[m,d] + h @ b_C'
// ---------------------------------------------------------------------------
#define KC_WS   (128 * 68)
#define KC_HS   (KC_WS + 64 * 68)
#define KC_SMEM (KC_HS + 128 * 17)

__global__ __launch_bounds__(256) void k_outC(const float* __restrict__ x,
                                              const float* __restrict__ W_C,
                                              const float* __restrict__ b_C,
                                              float* __restrict__ out) {
    extern __shared__ float sm[];
    float* Xs = sm;             // [128][68] tf32 x
    float* Ws = sm + KC_WS;     // [64][68]  tf32 W_C slice (reused for b_C)
    float* Hs = sm + KC_HS;     // [128][17] fp32 h
    const int tid = threadIdx.x;
    const int m0 = blockIdx.x * 128;

#pragma unroll
    for (int it = 0; it < 8; it++) {
        int i4 = it * 256 + tid;
        int row = i4 >> 4, c4 = (i4 & 15) * 4;
        float4 v = *(const float4*)&x[(long)(m0 + row) * 64 + c4];
        Xs[row * 68 + c4 + 0] = f2tf(v.x);
        Xs[row * 68 + c4 + 1] = f2tf(v.y);
        Xs[row * 68 + c4 + 2] = f2tf(v.z);
        Xs[row * 68 + c4 + 3] = f2tf(v.w);
    }
#pragma unroll
    for (int it = 0; it < 2; it++) {
        int i4 = it * 256 + tid;
        int row = i4 >> 2, c4 = (i4 & 3) * 4;
        float4 v = *(const float4*)&g_H[(long)(m0 + row) * DS + c4];
        Hs[row * 17 + c4 + 0] = v.x;
        Hs[row * 17 + c4 + 1] = v.y;
        Hs[row * 17 + c4 + 2] = v.z;
        Hs[row * 17 + c4 + 3] = v.w;
    }

    int wk[4], wd[4];
#pragma unroll
    for (int it = 0; it < 4; it++) {
        int i4 = it * 256 + tid;
        wk[it] = i4 >> 4;
        wd[it] = (i4 & 15) * 4;
    }
    float4 wreg[4];
#pragma unroll
    for (int it = 0; it < 4; it++)
        wreg[it] = *(const float4*)&W_C[(long)wk[it] * 1024 + wd[it]];   // n=0

    const int wid = tid >> 5, lane = tid & 31;
    const int g = lane >> 2, tig = lane & 3;
    const int wm = wid & 3, wn = wid >> 2;
    const int mbase = wm * 32, nbase = wn * 32;

    float oacc[2][4][4];
#pragma unroll
    for (int mt = 0; mt < 2; mt++)
#pragma unroll
        for (int nt = 0; nt < 4; nt++)
#pragma unroll
            for (int j = 0; j < 4; j++) oacc[mt][nt][j] = 0.f;

    for (int n = 0; n < 16; n++) {
        __syncthreads();
#pragma unroll
        for (int it = 0; it < 4; it++) {
            Ws[wk[it] * 68 + wd[it] + 0] = f2tf(wreg[it].x);
            Ws[wk[it] * 68 + wd[it] + 1] = f2tf(wreg[it].y);
            Ws[wk[it] * 68 + wd[it] + 2] = f2tf(wreg[it].z);
            Ws[wk[it] * 68 + wd[it] + 3] = f2tf(wreg[it].w);
        }
        __syncthreads();
        if (n + 1 < 16) {
#pragma unroll
            for (int it = 0; it < 4; it++)
                wreg[it] = *(const float4*)
                    &W_C[(long)wk[it] * 1024 + (n + 1) * 64 + wd[it]];
        }

        float c[2][4][4];
#pragma unroll
        for (int mt = 0; mt < 2; mt++)
#pragma unroll
            for (int nt = 0; nt < 4; nt++)
#pragma unroll
                for (int j = 0; j < 4; j++) c[mt][nt][j] = 0.f;

#pragma unroll
        for (int ks = 0; ks < 8; ks++) {
            const int k0 = ks * 8;
            unsigned a[2][4];
#pragma unroll
            for (int mt = 0; mt < 2; mt++) {
                int r = mbase + mt * 16 + g;
                a[mt][0] = fu(Xs[r * 68 + k0 + tig]);
                a[mt][1] = fu(Xs[(r + 8) * 68 + k0 + tig]);
                a[mt][2] = fu(Xs[r * 68 + k0 + tig + 4]);
                a[mt][3] = fu(Xs[(r + 8) * 68 + k0 + tig + 4]);
            }
            unsigned b[4][2];
#pragma unroll
            for (int nt = 0; nt < 4; nt++) {
                int nn = nbase + nt * 8 + g;
                b[nt][0] = fu(Ws[(k0 + tig) * 68 + nn]);
                b[nt][1] = fu(Ws[(k0 + tig + 4) * 68 + nn]);
            }
#pragma unroll
            for (int mt = 0; mt < 2; mt++)
#pragma unroll
                for (int nt = 0; nt < 4; nt++)
                    mma8(c[mt][nt], a[mt][0], a[mt][1], a[mt][2], a[mt][3],
                         b[nt][0], b[nt][1]);
        }

#pragma unroll
        for (int mt = 0; mt < 2; mt++) {
            int r0 = mbase + mt * 16 + g;
            float ha = Hs[r0 * 17 + n];
            float hb = Hs[(r0 + 8) * 17 + n];
#pragma unroll
            for (int nt = 0; nt < 4; nt++) {
                oacc[mt][nt][0] += ha * c[mt][nt][0];
                oacc[mt][nt][1] += ha * c[mt][nt][1];
                oacc[mt][nt][2] += hb * c[mt][nt][2];
                oacc[mt][nt][3] += hb * c[mt][nt][3];
            }
        }
    }

    __syncthreads();
    {
        int nn = tid >> 4, c4 = (tid & 15) * 4;
        float4 v = *(const float4*)&b_C[nn * 64 + c4];
        Ws[nn * 68 + c4 + 0] = v.x;
        Ws[nn * 68 + c4 + 1] = v.y;
        Ws[nn * 68 + c4 + 2] = v.z;
        Ws[nn * 68 + c4 + 3] = v.w;
    }
    __syncthreads();

#pragma unroll
    for (int mt = 0; mt < 2; mt++) {
        int r0 = mbase + mt * 16 + g;
        int r1 = r0 + 8;
#pragma unroll
        for (int nt = 0; nt < 4; nt++) {
            int col = nbase + nt * 8 + tig * 2;
            float s00 = 0.f, s01 = 0.f, s10 = 0.f, s11 = 0.f;
#pragma unroll
            for (int nn = 0; nn < 16; nn++) {
                float ha = Hs[r0 * 17 + nn], hb = Hs[r1 * 17 + nn];
                float w0 = Ws[nn * 68 + col], w1 = Ws[nn * 68 + col + 1];
                s00 += ha * w0; s01 += ha * w1;
                s10 += hb * w0; s11 += hb * w1;
            }
            *(float2*)&out[(long)(m0 + r0) * 64 + col] =
                make_float2(oacc[mt][nt][0] + s00, oacc[mt][nt][1] + s01);
            *(float2*)&out[(long)(m0 + r1) * 64 + col] =
                make_float2(oacc[mt][nt][2] + s10, oacc[mt][nt][3] + s11);
        }
    }
}

// ---------------------------------------------------------------------------
extern "C" void kernel_launch(void* const* d_in, const int* in_sizes, int n_in,
                              void* d_out, int out_size) {
    const float* x   = (const float*)d_in[0];
    const float* W_A = (const float*)d_in[1];
    const float* b_A = (const float*)d_in[2];
    const float* W_B = (const float*)d_in[3];
    const float* b_B = (const float*)d_in[4];
    const float* W_C = (const float*)d_in[5];
    const float* b_C = (const float*)d_in[6];
    float* out = (float*)d_out;

    const int smP = KP_SMEM * sizeof(float);
    const int smC = CK_SMEM * sizeof(float);
    const int smO = KC_SMEM * sizeof(float);
    cudaFuncSetAttribute(k_proj,  cudaFuncAttributeMaxDynamicSharedMemorySize, smP);
    cudaFuncSetAttribute(k_chunk, cudaFuncAttributeMaxDynamicSharedMemorySize, smC);
    cudaFuncSetAttribute(k_outC,  cudaFuncAttributeMaxDynamicSharedMemorySize, smO);

    k_proj<<<dim3(ROWS / 128, 2), 256, smP>>>(x, W_A, b_A, W_B, b_B);
    k_chunk<<<BATCH * NCHUNK, 256, smC>>>();
    k_super<<<BATCH * NSUPER, 256>>>();
    k_scan2<<<BATCH, 32>>>();
    k_mid<<<BATCH * NSUPER, 32>>>();
    k_replay<<<BATCH * NCHUNK, 32>>>();
    k_outC<<<ROWS / 128, 256, smO>>>(x, W_C, b_C, out);
}